// round 6
// baseline (speedup 1.0000x reference)
#include <cuda_runtime.h>

static constexpr int NU = 500000;
static constexpr int NI = 100000;
static constexpr int F  = 300;
static constexpr int D  = 64;
static constexpr int E  = 2000000;
static constexpr int EL = 1000000;

static constexpr int TILES_I = (NI + 127) / 128;   // 782
static constexpr int TILES_U = (NU + 127) / 128;   // 3907
static constexpr int EBLK    = (E + 255) / 256;    // 7813
static constexpr int NB_I    = (NI + 2047) / 2048; // 49
static constexpr int NB_U    = (NU + 2047) / 2048; // 245
static constexpr int CB_I    = (NI + 255) / 256;   // 391
static constexpr int CB_U    = (NU + 255) / 256;   // 1954

// ---------------- device scratch ----------------
__device__ float g_xi  [NI * D];
__device__ float g_xiT [NI * D];
__device__ float g_hi  [NI * D];
__device__ float g_hi2 [NI * D];
__device__ float g_hu  [NU * D];
__device__ float g_hu2 [NU * D];
__device__ int   g_degI[NI];
__device__ int   g_degU[NU];
__device__ int   g_offI[NI + 1];
__device__ int   g_offU[NU + 1];
__device__ int   g_curI[NI];
__device__ int   g_curU[NU];
__device__ int   g_csrI[E];
__device__ int   g_csrU[E];
__device__ int   g_bsumI[64];
__device__ int   g_bsumU[256];

// ---------------- helpers ----------------
__device__ __forceinline__ unsigned long long pk2(float a, float b) {
    float2 t = make_float2(a, b);
    return *reinterpret_cast<unsigned long long*>(&t);
}
__device__ __forceinline__ float2 upk(unsigned long long v) {
    return *reinterpret_cast<float2*>(&v);
}
__device__ __forceinline__ unsigned long long ffma2(unsigned long long a,
                                                    unsigned long long b,
                                                    unsigned long long c) {
    unsigned long long d;
    asm("fma.rn.f32x2 %0, %1, %2, %3;" : "=l"(d) : "l"(a), "l"(b), "l"(c));
    return d;
}

// ---------------- GEMM inner pass (tile 128x64, 256 thr, 4x8 per thread) ----------------
#define GEMM_PASS(ACC)                                                            \
    _Pragma("unroll")                                                             \
    for (int kb = 0; kb < 16; kb++) {                                             \
        float4 xv[4];                                                             \
        _Pragma("unroll")                                                         \
        for (int i = 0; i < 4; i++) {                                             \
            int r = ty + 32 * i;                                                  \
            xv[i] = Xs[r * 16 + (kb ^ (r & 15))];                                 \
        }                                                                         \
        _Pragma("unroll")                                                         \
        for (int q = 0; q < 4; q++) {                                             \
            int k = kb * 4 + q;                                                   \
            ulonglong2 wA = *reinterpret_cast<const ulonglong2*>(Ws + k * 16 + tx * 2);     \
            ulonglong2 wB = *reinterpret_cast<const ulonglong2*>(Ws + k * 16 + tx * 2 + 1); \
            _Pragma("unroll")                                                     \
            for (int i = 0; i < 4; i++) {                                         \
                float a = (q == 0) ? xv[i].x : (q == 1) ? xv[i].y                 \
                        : (q == 2) ? xv[i].z : xv[i].w;                           \
                unsigned long long a2 = pk2(a, a);                                \
                ACC[i][0] = ffma2(a2, wA.x, ACC[i][0]);                           \
                ACC[i][1] = ffma2(a2, wA.y, ACC[i][1]);                           \
                ACC[i][2] = ffma2(a2, wB.x, ACC[i][2]);                           \
                ACC[i][3] = ffma2(a2, wB.y, ACC[i][3]);                           \
            }                                                                     \
        }                                                                         \
    }

// 32-k variant (8 kb blocks, 8-f4 row stride, swizzle mod 8)
#define GEMM_PASS32(ACC, XS, WS)                                                  \
    _Pragma("unroll")                                                             \
    for (int kb = 0; kb < 8; kb++) {                                              \
        float4 xv[4];                                                             \
        _Pragma("unroll")                                                         \
        for (int i = 0; i < 4; i++) {                                             \
            int r = ty + 32 * i;                                                  \
            xv[i] = XS[r * 8 + (kb ^ (r & 7))];                                   \
        }                                                                         \
        _Pragma("unroll")                                                         \
        for (int q = 0; q < 4; q++) {                                             \
            int k = kb * 4 + q;                                                   \
            ulonglong2 wA = *reinterpret_cast<const ulonglong2*>(WS + k * 16 + tx * 2);     \
            ulonglong2 wB = *reinterpret_cast<const ulonglong2*>(WS + k * 16 + tx * 2 + 1); \
            _Pragma("unroll")                                                     \
            for (int i = 0; i < 4; i++) {                                         \
                float a = (q == 0) ? xv[i].x : (q == 1) ? xv[i].y                 \
                        : (q == 2) ? xv[i].z : xv[i].w;                           \
                unsigned long long a2 = pk2(a, a);                                \
                ACC[i][0] = ffma2(a2, wA.x, ACC[i][0]);                           \
                ACC[i][1] = ffma2(a2, wA.y, ACC[i][1]);                           \
                ACC[i][2] = ffma2(a2, wB.x, ACC[i][2]);                           \
                ACC[i][3] = ffma2(a2, wB.y, ACC[i][3]);                           \
            }                                                                     \
        }                                                                         \
    }

// ---------------- CSR build pieces (fused over both node types) ----------------
__global__ void k_zero_deg() {
    int i = blockIdx.x * blockDim.x + threadIdx.x;
    if (i < NU) { g_degU[i] = 0; g_curU[i] = 0; }
    if (i < NI) { g_degI[i] = 0; g_curI[i] = 0; }
}

__global__ void k_scan_a() {
    const int* deg; int n; int* out; int* bsum; int blk;
    if (blockIdx.x < NB_I) { deg = g_degI; n = NI; out = g_offI; bsum = g_bsumI; blk = blockIdx.x; }
    else                   { deg = g_degU; n = NU; out = g_offU; bsum = g_bsumU; blk = blockIdx.x - NB_I; }

    __shared__ int ws[8];
    const int t = threadIdx.x;
    const int base = blk * 2048 + t * 8;
    int v[8];
    #pragma unroll
    for (int j = 0; j < 8; j++) v[j] = (base + j < n) ? deg[base + j] : 0;
    int s = 0;
    #pragma unroll
    for (int j = 0; j < 8; j++) { int x = v[j]; v[j] = s; s += x; }
    const int lane = t & 31, wid = t >> 5;
    int sx = s;
    #pragma unroll
    for (int o = 1; o < 32; o <<= 1) {
        int y = __shfl_up_sync(0xffffffffu, sx, o);
        if (lane >= o) sx += y;
    }
    if (lane == 31) ws[wid] = sx;
    __syncthreads();
    if (wid == 0 && lane < 8) {
        int b = ws[lane];
        int bx = b;
        #pragma unroll
        for (int o = 1; o < 8; o <<= 1) {
            int y = __shfl_up_sync(0xffu, bx, o);
            if (lane >= o) bx += y;
        }
        ws[lane] = bx - b;
        if (lane == 7) bsum[blk] = bx;
    }
    __syncthreads();
    const int off = ws[wid] + (sx - s);
    #pragma unroll
    for (int j = 0; j < 8; j++)
        if (base + j < n) out[base + j] = off + v[j];
}

__global__ void k_scan_b() {
    int* bsum; int nb;
    if (blockIdx.x == 0) { bsum = g_bsumI; nb = NB_I; }
    else                 { bsum = g_bsumU; nb = NB_U; }
    __shared__ int sm[256];
    const int t = threadIdx.x;
    int v = (t < nb) ? bsum[t] : 0;
    sm[t] = v;
    __syncthreads();
    for (int o = 1; o < 256; o <<= 1) {
        int y = (t >= o) ? sm[t - o] : 0;
        __syncthreads();
        sm[t] += y;
        __syncthreads();
    }
    if (t < nb) bsum[t] = sm[t] - v;
}

__global__ void k_scan_c() {
    if (blockIdx.x < CB_I) {
        int i = blockIdx.x * 256 + threadIdx.x;
        if (i < NI) g_offI[i] += g_bsumI[i >> 11];
        if (i == 0) g_offI[NI] = E;
    } else {
        int i = (blockIdx.x - CB_I) * 256 + threadIdx.x;
        if (i < NU) g_offU[i] += g_bsumU[i >> 11];
        if (i == 0) g_offU[NU] = E;
    }
}

// ============================================================================
// fused: pipelined item input linear (blocks < TILES_I) || degree count
// ============================================================================
__global__ __launch_bounds__(256) void k_lin_count(
    const float* __restrict__ X, const float* __restrict__ W,
    const float* __restrict__ bias, float* __restrict__ Y,
    const int* __restrict__ es, const int* __restrict__ ed)
{
    if (blockIdx.x >= TILES_I) {
        int i = (int)(blockIdx.x - TILES_I) * 256 + threadIdx.x;
        if (i < E) {
            atomicAdd(&g_degU[es[i]], 1);
            atomicAdd(&g_degI[ed[i]], 1);
        }
        return;
    }
    __shared__ float4 XsB[2][1024];   // 2 x 16 KB  (128 rows x 32 k)
    __shared__ float4 WsB[2][512];    // 2 x 8 KB   (32 k x 64 cols)
    const int tid = threadIdx.x;
    const int tx  = (tid >> 2) & 7;
    const int ty  = (tid >> 5) * 4 + (tid & 3);
    const int tile = blockIdx.x * 128;

    // per-thread load coordinates
    const int xr0 = tid >> 1;              // X: 4 f4/thread at f = tid + j*256 -> row=f>>3,c4=f&7
    const int wk0 = tid >> 4;              // W: 2 f4/thread at f = tid + j*256 -> k=f>>4,c4=f&15
    (void)xr0; (void)wk0;

    // register prefetch buffers
    float4 px[4];
    float4 pw[2];

    auto loadChunk = [&](int kc, float4* pxr, float4* pwr) {
        const int k0 = kc * 32;
        const int kn = (k0 + 32 <= F) ? 32 : (F - k0);    // 32 ... last = 12
        #pragma unroll
        for (int j = 0; j < 4; j++) {
            int f = tid + j * 256;
            int row = f >> 3, c4 = f & 7;
            int rg = tile + row;
            float4 v = make_float4(0.f, 0.f, 0.f, 0.f);
            if (rg < NI && c4 * 4 < kn)
                v = *reinterpret_cast<const float4*>(X + rg * F + k0 + c4 * 4);
            pxr[j] = v;
        }
        #pragma unroll
        for (int j = 0; j < 2; j++) {
            int f = tid + j * 256;
            int k = f >> 4, c4 = f & 15;
            float4 v = make_float4(0.f, 0.f, 0.f, 0.f);
            if (k < kn) v = reinterpret_cast<const float4*>(W + (k0 + k) * 64)[c4];
            pwr[j] = v;
        }
    };
    auto storeChunk = [&](int b, const float4* pxr, const float4* pwr) {
        #pragma unroll
        for (int j = 0; j < 4; j++) {
            int f = tid + j * 256;
            int row = f >> 3, c4 = f & 7;
            XsB[b][row * 8 + (c4 ^ (row & 7))] = pxr[j];
        }
        #pragma unroll
        for (int j = 0; j < 2; j++)
            WsB[b][tid + j * 256] = pwr[j];
    };

    unsigned long long acc[4][4];
    {
        const float* bp = bias + tx * 8;
        unsigned long long b0 = pk2(bp[0], bp[1]), b1 = pk2(bp[2], bp[3]);
        unsigned long long b2 = pk2(bp[4], bp[5]), b3 = pk2(bp[6], bp[7]);
        #pragma unroll
        for (int i = 0; i < 4; i++) {
            acc[i][0] = b0; acc[i][1] = b1; acc[i][2] = b2; acc[i][3] = b3;
        }
    }

    // prologue: chunk 0 into buffer 0
    loadChunk(0, px, pw);
    storeChunk(0, px, pw);
    __syncthreads();

    #pragma unroll 1
    for (int c = 0; c < 10; c++) {           // 10 chunks of 32 (300 = 9*32 + 12)
        if (c < 9) loadChunk(c + 1, px, pw); // LDG in flight during compute
        {
            const float4* Xs = XsB[c & 1];
            const float4* Ws = WsB[c & 1];
            GEMM_PASS32(acc, Xs, Ws)
        }
        if (c < 9) storeChunk((c + 1) & 1, px, pw);
        __syncthreads();
    }

    #pragma unroll
    for (int i = 0; i < 4; i++) {
        int rg = tile + ty + 32 * i;
        if (rg < NI) {
            float2 r0 = upk(acc[i][0]), r1 = upk(acc[i][1]);
            float2 r2 = upk(acc[i][2]), r3 = upk(acc[i][3]);
            float4* yp = reinterpret_cast<float4*>(Y + rg * 64 + tx * 8);
            yp[0] = make_float4(r0.x, r0.y, r1.x, r1.y);
            yp[1] = make_float4(r2.x, r2.y, r3.x, r3.y);
        }
    }
}

// ---------------- plain GEMM tile body (Y = X @ W, N rows) ----------------
__device__ __forceinline__ void gemm_tile(
    int tile, const float* __restrict__ X, const float* __restrict__ W,
    float* __restrict__ Y, int N, float4* Xs, float4* Ws)
{
    const int tid = threadIdx.x;
    const int tx  = (tid >> 2) & 7;
    const int ty  = (tid >> 5) * 4 + (tid & 3);

    #pragma unroll
    for (int j = 0; j < 4; j++)
        Ws[tid + j * 256] = reinterpret_cast<const float4*>(W)[tid + j * 256];
    #pragma unroll
    for (int j = 0; j < 8; j++) {
        int f = tid + j * 256;
        int row = f >> 4, c4 = f & 15;
        int rg = tile + row;
        float4 v = make_float4(0.f, 0.f, 0.f, 0.f);
        if (rg < N) v = reinterpret_cast<const float4*>(X)[rg * 16 + c4];
        Xs[row * 16 + (c4 ^ (row & 15))] = v;
    }
    __syncthreads();

    unsigned long long acc[4][4];
    #pragma unroll
    for (int i = 0; i < 4; i++)
        #pragma unroll
        for (int t = 0; t < 4; t++) acc[i][t] = 0ull;

    GEMM_PASS(acc)

    #pragma unroll
    for (int i = 0; i < 4; i++) {
        int rg = tile + ty + 32 * i;
        if (rg < N) {
            float2 r0 = upk(acc[i][0]), r1 = upk(acc[i][1]);
            float2 r2 = upk(acc[i][2]), r3 = upk(acc[i][3]);
            float4* yp = reinterpret_cast<float4*>(Y + rg * 64 + tx * 8);
            yp[0] = make_float4(r0.x, r0.y, r1.x, r1.y);
            yp[1] = make_float4(r2.x, r2.y, r3.x, r3.y);
        }
    }
}

// ============================================================================
// fused: gemm (xiT = xi @ Wl_iu) || csr fill
// ============================================================================
__global__ __launch_bounds__(256) void k_gemm_fill(
    const float* __restrict__ X, const float* __restrict__ W, float* __restrict__ Y,
    const int* __restrict__ es, const int* __restrict__ ed)
{
    if (blockIdx.x >= TILES_I) {
        int e = (int)(blockIdx.x - TILES_I) * 256 + threadIdx.x;
        if (e < E) {
            int u = es[e], it = ed[e];
            g_csrI[g_offI[it] + atomicAdd(&g_curI[it], 1)] = u;
            g_csrU[g_offU[u] + atomicAdd(&g_curU[u], 1)] = it;
        }
        return;
    }
    __shared__ float4 Xs[2048];
    __shared__ float4 Ws[1024];
    gemm_tile(blockIdx.x * 128, X, W, Y, NI, Xs, Ws);
}

__global__ __launch_bounds__(256) void k_gemm(
    const float* __restrict__ X, const float* __restrict__ W, float* __restrict__ Y, int N)
{
    __shared__ float4 Xs[2048];
    __shared__ float4 Ws[1024];
    gemm_tile(blockIdx.x * 128, X, W, Y, N, Xs, Ws);
}

// ---------------- 4-edge unrolled gather-mean into a[8] ----------------
__device__ __forceinline__ void gather_mean(
    const float* __restrict__ feat, const int* __restrict__ csr,
    int p0, int p1, int tx, float* a)
{
    float s[8];
    #pragma unroll
    for (int t = 0; t < 8; t++) s[t] = 0.f;
    int p = p0;
    for (; p + 4 <= p1; p += 4) {
        int i0 = csr[p], i1 = csr[p + 1], i2 = csr[p + 2], i3 = csr[p + 3];
        const float4* f0 = reinterpret_cast<const float4*>(feat + i0 * 64 + tx * 8);
        const float4* f1 = reinterpret_cast<const float4*>(feat + i1 * 64 + tx * 8);
        const float4* f2 = reinterpret_cast<const float4*>(feat + i2 * 64 + tx * 8);
        const float4* f3 = reinterpret_cast<const float4*>(feat + i3 * 64 + tx * 8);
        float4 a0 = f0[0], a1 = f0[1], b0 = f1[0], b1 = f1[1];
        float4 c0 = f2[0], c1 = f2[1], d0 = f3[0], d1 = f3[1];
        s[0] += (a0.x + b0.x) + (c0.x + d0.x);
        s[1] += (a0.y + b0.y) + (c0.y + d0.y);
        s[2] += (a0.z + b0.z) + (c0.z + d0.z);
        s[3] += (a0.w + b0.w) + (c0.w + d0.w);
        s[4] += (a1.x + b1.x) + (c1.x + d1.x);
        s[5] += (a1.y + b1.y) + (c1.y + d1.y);
        s[6] += (a1.z + b1.z) + (c1.z + d1.z);
        s[7] += (a1.w + b1.w) + (c1.w + d1.w);
    }
    if (p + 2 <= p1) {
        int i0 = csr[p], i1 = csr[p + 1];
        const float4* f0 = reinterpret_cast<const float4*>(feat + i0 * 64 + tx * 8);
        const float4* f1 = reinterpret_cast<const float4*>(feat + i1 * 64 + tx * 8);
        float4 a0 = f0[0], a1 = f0[1], b0 = f1[0], b1 = f1[1];
        s[0] += a0.x + b0.x; s[1] += a0.y + b0.y;
        s[2] += a0.z + b0.z; s[3] += a0.w + b0.w;
        s[4] += a1.x + b1.x; s[5] += a1.y + b1.y;
        s[6] += a1.z + b1.z; s[7] += a1.w + b1.w;
        p += 2;
    }
    if (p < p1) {
        int i0 = csr[p];
        const float4* f0 = reinterpret_cast<const float4*>(feat + i0 * 64 + tx * 8);
        float4 a0 = f0[0], a1 = f0[1];
        s[0] += a0.x; s[1] += a0.y; s[2] += a0.z; s[3] += a0.w;
        s[4] += a1.x; s[5] += a1.y; s[6] += a1.z; s[7] += a1.w;
    }
    float rc = 1.f / fmaxf((float)(p1 - p0), 1.f);
    #pragma unroll
    for (int t = 0; t < 8; t++) a[t] += rc * s[t];
}

// ============================================================================
// fused node update: item tiles (blocks < TILES_I) || user tiles (rest)
// ============================================================================
__device__ __forceinline__ void item_tile(
    int tile,
    const float* __restrict__ srcFeat,
    const int* __restrict__ off, const int* __restrict__ csr,
    const float* __restrict__ Wl,
    const float* __restrict__ X, const float* __restrict__ Wr,
    const float* __restrict__ bias, int relu, float* __restrict__ Y,
    float4* Xs, float4* Ws)
{
    const int tid = threadIdx.x;
    const int tx  = (tid >> 2) & 7;
    const int ty  = (tid >> 5) * 4 + (tid & 3);

    // phase A: gather-mean src rows into Xs
    #pragma unroll 1
    for (int i = 0; i < 4; i++) {
        const int r  = ty + 32 * i;
        const int rg = tile + r;
        float a[8];
        #pragma unroll
        for (int t = 0; t < 8; t++) a[t] = 0.f;
        if (rg < NI) {
            int p0 = off[rg], p1 = off[rg + 1];
            gather_mean(srcFeat, csr, p0, p1, tx, a);
        }
        Xs[r * 16 + ((tx * 2)     ^ (r & 15))] = make_float4(a[0], a[1], a[2], a[3]);
        Xs[r * 16 + ((tx * 2 + 1) ^ (r & 15))] = make_float4(a[4], a[5], a[6], a[7]);
    }
    #pragma unroll
    for (int j = 0; j < 4; j++)
        Ws[tid + j * 256] = reinterpret_cast<const float4*>(Wl)[tid + j * 256];
    __syncthreads();

    unsigned long long acc[4][4];
    {
        const float* bp = bias + tx * 8;
        unsigned long long b0 = pk2(bp[0], bp[1]), b1 = pk2(bp[2], bp[3]);
        unsigned long long b2 = pk2(bp[4], bp[5]), b3 = pk2(bp[6], bp[7]);
        #pragma unroll
        for (int i = 0; i < 4; i++) {
            acc[i][0] = b0; acc[i][1] = b1; acc[i][2] = b2; acc[i][3] = b3;
        }
    }
    GEMM_PASS(acc)

    // phase B: X @ Wr
    __syncthreads();
    #pragma unroll
    for (int j = 0; j < 8; j++) {
        int f = tid + j * 256;
        int row = f >> 4, c4 = f & 15;
        int rg = tile + row;
        float4 v = make_float4(0.f, 0.f, 0.f, 0.f);
        if (rg < NI) v = reinterpret_cast<const float4*>(X)[rg * 16 + c4];
        Xs[row * 16 + (c4 ^ (row & 15))] = v;
    }
    #pragma unroll
    for (int j = 0; j < 4; j++)
        Ws[tid + j * 256] = reinterpret_cast<const float4*>(Wr)[tid + j * 256];
    __syncthreads();
    GEMM_PASS(acc)

    #pragma unroll
    for (int i = 0; i < 4; i++) {
        int rg = tile + ty + 32 * i;
        if (rg < NI) {
            float2 r0 = upk(acc[i][0]), r1 = upk(acc[i][1]);
            float2 r2 = upk(acc[i][2]), r3 = upk(acc[i][3]);
            float y[8] = { r0.x, r0.y, r1.x, r1.y, r2.x, r2.y, r3.x, r3.y };
            if (relu) {
                #pragma unroll
                for (int t = 0; t < 8; t++) y[t] = fmaxf(y[t], 0.f);
            }
            float4* yp = reinterpret_cast<float4*>(Y + rg * 64 + tx * 8);
            yp[0] = make_float4(y[0], y[1], y[2], y[3]);
            yp[1] = make_float4(y[4], y[5], y[6], y[7]);
        }
    }
}

__device__ __forceinline__ void user_tile(
    int tile,
    const float* __restrict__ gsrc,
    const int* __restrict__ off, const int* __restrict__ csr,
    const float* __restrict__ X, const float* __restrict__ Wr,
    const float* __restrict__ bias, int relu, float* __restrict__ Y,
    float4* Xs, float4* Ws)
{
    const int tid = threadIdx.x;
    const int tx  = (tid >> 2) & 7;
    const int ty  = (tid >> 5) * 4 + (tid & 3);

    #pragma unroll
    for (int j = 0; j < 4; j++)
        Ws[tid + j * 256] = reinterpret_cast<const float4*>(Wr)[tid + j * 256];
    #pragma unroll
    for (int j = 0; j < 8; j++) {
        int f = tid + j * 256;
        int row = f >> 4, c4 = f & 15;
        int rg = tile + row;
        float4 v = make_float4(0.f, 0.f, 0.f, 0.f);
        if (rg < NU) v = reinterpret_cast<const float4*>(X)[rg * 16 + c4];
        Xs[row * 16 + (c4 ^ (row & 15))] = v;
    }
    __syncthreads();

    unsigned long long acc[4][4];
    #pragma unroll 1
    for (int i = 0; i < 4; i++) {
        const int rg = tile + ty + 32 * i;
        float a[8];
        {
            const float* bp = bias + tx * 8;
            #pragma unroll
            for (int t = 0; t < 8; t++) a[t] = bp[t];
        }
        if (rg < NU) {
            int p0 = off[rg], p1 = off[rg + 1];
            gather_mean(gsrc, csr, p0, p1, tx, a);
        }
        acc[i][0] = pk2(a[0], a[1]); acc[i][1] = pk2(a[2], a[3]);
        acc[i][2] = pk2(a[4], a[5]); acc[i][3] = pk2(a[6], a[7]);
    }

    GEMM_PASS(acc)

    #pragma unroll
    for (int i = 0; i < 4; i++) {
        int rg = tile + ty + 32 * i;
        if (rg < NU) {
            float2 r0 = upk(acc[i][0]), r1 = upk(acc[i][1]);
            float2 r2 = upk(acc[i][2]), r3 = upk(acc[i][3]);
            float y[8] = { r0.x, r0.y, r1.x, r1.y, r2.x, r2.y, r3.x, r3.y };
            if (relu) {
                #pragma unroll
                for (int t = 0; t < 8; t++) y[t] = fmaxf(y[t], 0.f);
            }
            float4* yp = reinterpret_cast<float4*>(Y + rg * 64 + tx * 8);
            yp[0] = make_float4(y[0], y[1], y[2], y[3]);
            yp[1] = make_float4(y[4], y[5], y[6], y[7]);
        }
    }
}

__global__ __launch_bounds__(256) void k_upd(
    const float* __restrict__ itemGsrc, const float* __restrict__ Wl_ui,
    const float* __restrict__ itemX, const float* __restrict__ Wr_ui,
    const float* __restrict__ b_ui, float* __restrict__ Yi,
    const float* __restrict__ userGsrc, const float* __restrict__ userX,
    const float* __restrict__ Wr_iu, const float* __restrict__ b_iu,
    float* __restrict__ Yu,
    int relu)
{
    __shared__ float4 Xs[2048];
    __shared__ float4 Ws[1024];
    if (blockIdx.x < TILES_I) {
        item_tile(blockIdx.x * 128, itemGsrc, g_offI, g_csrI, Wl_ui, itemX, Wr_ui,
                  b_ui, relu, Yi, Xs, Ws);
    } else {
        user_tile((int)(blockIdx.x - TILES_I) * 128, userGsrc, g_offU, g_csrU,
                  userX, Wr_iu, b_iu, relu, Yu, Xs, Ws);
    }
}

// ---------------- predictor ----------------
__global__ void k_dot(const float* __restrict__ hu, const float* __restrict__ hi,
                      const int* __restrict__ ls, const int* __restrict__ ld,
                      float* __restrict__ out) {
    int i = blockIdx.x * blockDim.x + threadIdx.x;
    int e = i >> 3;
    int j = i & 7;
    if (e >= EL) return;
    int u = ls[e];
    int v = ld[e];
    const float4* pa = reinterpret_cast<const float4*>(hu + u * 64 + j * 8);
    const float4* pb = reinterpret_cast<const float4*>(hi + v * 64 + j * 8);
    float4 a0 = pa[0], a1 = pa[1], b0 = pb[0], b1 = pb[1];
    float s = a0.x * b0.x + a0.y * b0.y + a0.z * b0.z + a0.w * b0.w
            + a1.x * b1.x + a1.y * b1.y + a1.z * b1.z + a1.w * b1.w;
    s += __shfl_down_sync(0xffffffffu, s, 4, 8);
    s += __shfl_down_sync(0xffffffffu, s, 2, 8);
    s += __shfl_down_sync(0xffffffffu, s, 1, 8);
    if (j == 0) out[e] = s;
}

// ---------------- launch ----------------
extern "C" void kernel_launch(void* const* d_in, const int* in_sizes, int n_in,
                              void* d_out, int out_size) {
    const float* user_emb = (const float*)d_in[0];
    const float* item_x   = (const float*)d_in[1];
    const float* Wlin     = (const float*)d_in[2];
    const float* blin     = (const float*)d_in[3];
    const float* Wl1_ui   = (const float*)d_in[4];
    const float* Wr1_ui   = (const float*)d_in[5];
    const float* b1_ui    = (const float*)d_in[6];
    const float* Wl1_iu   = (const float*)d_in[7];
    const float* Wr1_iu   = (const float*)d_in[8];
    const float* b1_iu    = (const float*)d_in[9];
    const float* Wl2_ui   = (const float*)d_in[10];
    const float* Wr2_ui   = (const float*)d_in[11];
    const float* b2_ui    = (const float*)d_in[12];
    const float* Wl2_iu   = (const float*)d_in[13];
    const float* Wr2_iu   = (const float*)d_in[14];
    const float* b2_iu    = (const float*)d_in[15];
    const int* es   = (const int*)d_in[17];
    const int* ed   = (const int*)d_in[18];
    const int* ls   = (const int*)d_in[19];
    const int* ldst = (const int*)d_in[20];
    float* out = (float*)d_out;

    float *xi, *xiT, *hu, *hi, *hu2, *hi2;
    cudaGetSymbolAddress((void**)&xi,   g_xi);
    cudaGetSymbolAddress((void**)&xiT,  g_xiT);
    cudaGetSymbolAddress((void**)&hu,   g_hu);
    cudaGetSymbolAddress((void**)&hi,   g_hi);
    cudaGetSymbolAddress((void**)&hu2,  g_hu2);
    cudaGetSymbolAddress((void**)&hi2,  g_hi2);

    // 0: zero degrees
    k_zero_deg<<<(NU + 255) / 256, 256>>>();
    // 1: fused [pipelined item linear || degree count]
    k_lin_count<<<TILES_I + EBLK, 256>>>(item_x, Wlin, blin, xi, es, ed);
    // 2-4: fused scans (both node types per launch)
    k_scan_a<<<NB_I + NB_U, 256>>>();
    k_scan_b<<<2, 256>>>();
    k_scan_c<<<CB_I + CB_U, 256>>>();
    // 5: fused [xiT1 = xi @ Wl1_iu || csr fill]
    k_gemm_fill<<<TILES_I + EBLK, 256>>>(xi, Wl1_iu, xiT, es, ed);
    // 6: layer 1 fused [item update || user update]
    k_upd<<<TILES_I + TILES_U, 256>>>(user_emb, Wl1_ui, xi, Wr1_ui, b1_ui, hi,
                                      xiT, user_emb, Wr1_iu, b1_iu, hu, 1);
    // 7: xiT2 = hi @ Wl2_iu
    k_gemm<<<TILES_I, 256>>>(hi, Wl2_iu, xiT, NI);
    // 8: layer 2 fused
    k_upd<<<TILES_I + TILES_U, 256>>>(hu, Wl2_ui, hi, Wr2_ui, b2_ui, hi2,
                                      xiT, hu, Wr2_iu, b2_iu, hu2, 0);
    // 9: predictor
    k_dot<<<(EL * 8) / 256, 256>>>(hu2, hi2, ls, ldst, out);
}